// round 12
// baseline (speedup 1.0000x reference)
#include <cuda_runtime.h>
#include <cuda_fp16.h>
#include <mma.h>
using namespace nvcuda;

// Fixed problem shape (SimpleGNN): N=100000 nodes, E=1600000 edges, dims 64->64->64
#define MAXN 100000
#define MAXE 1600000

// Scratch (device globals -- no runtime allocation allowed)
__device__ __half g_hbuf[MAXN * 64];   // fp16 pre-scaled message table (layer 1)
__device__ __half g_hact[MAXN * 64];   // fp16 pre-scaled message table (layer 2)
__device__ int    g_indeg[MAXN];       // re-zeroed in k_scan3 (replay invariant)
__device__ int    g_incl[MAXN];
__device__ int    g_offs[MAXN + 1];    // exclusive offsets (immutable after scan3)
__device__ int    g_rank[MAXE];        // within-node rank of each edge (from hist)
__device__ int    g_csr[MAXE];         // src index only (weight folded into message)
__device__ float  g_dinv[MAXN];
__device__ int    g_bsums[128];        // per-1024-block totals from scan1

__device__ __forceinline__ unsigned h2_bits(__half2 h) {
    return *reinterpret_cast<unsigned*>(&h);
}
__device__ __forceinline__ float2 h2f2(unsigned bits) {
    return __half22float2(*reinterpret_cast<__half2*>(&bits));
}

// ---------------------------------------------------------------------------
// Histogram of in-degrees + per-edge rank (position within its node's segment)
// ---------------------------------------------------------------------------
__global__ void k_hist(const int* __restrict__ dst, int E) {
    int i = (blockIdx.x * blockDim.x + threadIdx.x) * 4;
    if (i + 4 <= E) {
        int4 d = __ldg((const int4*)(dst + i));
        int4 r;
        r.x = atomicAdd(&g_indeg[d.x], 1);
        r.y = atomicAdd(&g_indeg[d.y], 1);
        r.z = atomicAdd(&g_indeg[d.z], 1);
        r.w = atomicAdd(&g_indeg[d.w], 1);
        *(int4*)(g_rank + i) = r;
    } else {
        for (; i < E; i++) g_rank[i] = atomicAdd(&g_indeg[dst[i]], 1);
    }
}

// Block-wise inclusive scan of indeg (shfl); block totals -> g_bsums.
// Also emits dinv = rsqrt(indeg+1) so GEMM1 can fork right after this kernel.
__global__ __launch_bounds__(1024) void k_scan1(int n) {
    __shared__ int wsum[32];
    int t = threadIdx.x, lane = t & 31, w = t >> 5;
    int i = blockIdx.x * 1024 + t;
    int v = (i < n) ? g_indeg[i] : 0;
    int x = v;
    #pragma unroll
    for (int d = 1; d < 32; d <<= 1) {
        int y = __shfl_up_sync(0xffffffffu, x, d);
        if (lane >= d) x += y;
    }
    if (lane == 31) wsum[w] = x;
    __syncthreads();
    if (w == 0) {
        int y = wsum[lane];
        int z = y;
        #pragma unroll
        for (int d = 1; d < 32; d <<= 1) {
            int u = __shfl_up_sync(0xffffffffu, z, d);
            if (lane >= d) z += u;
        }
        wsum[lane] = z - y;  // exclusive warp offsets
    }
    __syncthreads();
    x += wsum[w];
    if (i < n) {
        g_incl[i] = x;
        g_dinv[i] = rsqrtf((float)(v + 1));
    }
    if (t == 1023) g_bsums[blockIdx.x] = x;
}

// Offsets: each 256-block lies in one 1024-chunk; warp 0 reduces bsums[0..chunk)
// (<=98 ints). Re-zeroes indeg for the next replay.
__global__ void k_scan3(int n) {
    __shared__ int s_pre;
    int chunk = (blockIdx.x * 256) >> 10;
    if (threadIdx.x < 32) {
        int acc = 0;
        for (int k = threadIdx.x; k < chunk; k += 32) acc += g_bsums[k];
        #pragma unroll
        for (int d = 16; d >= 1; d >>= 1) acc += __shfl_down_sync(0xffffffffu, acc, d);
        if (threadIdx.x == 0) s_pre = acc;
    }
    __syncthreads();
    int i = blockIdx.x * 256 + threadIdx.x;
    if (i < n) {
        int ind = g_indeg[i];
        int base = s_pre + g_incl[i];
        g_offs[i] = base - ind;
        if (i == n - 1) g_offs[n] = base;
        g_indeg[i] = 0;                      // ready for next replay
    }
}

// Atomic-free scatter: pos = offs[dst] + rank (rank precomputed in hist).
__global__ void k_fill(const int* __restrict__ src, const int* __restrict__ dst, int E) {
    int i = (blockIdx.x * blockDim.x + threadIdx.x) * 4;
    if (i + 4 <= E) {
        int4 s = __ldg((const int4*)(src + i));
        int4 d = __ldg((const int4*)(dst + i));
        int4 r = *(const int4*)(g_rank + i);
        g_csr[__ldg(&g_offs[d.x]) + r.x] = s.x;
        g_csr[__ldg(&g_offs[d.y]) + r.y] = s.y;
        g_csr[__ldg(&g_offs[d.z]) + r.z] = s.z;
        g_csr[__ldg(&g_offs[d.w]) + r.w] = s.w;
    } else {
        for (; i < E; i++) {
            g_csr[__ldg(&g_offs[dst[i]]) + g_rank[i]] = src[i];
        }
    }
}

#define XLD 72   // smem tile leading dim (halves); 144B, multiple of 16B
#define SLD 20   // scratch leading dim (floats); 80B, multiple of 16B

// ---------------------------------------------------------------------------
// Warp-level aggregation of one node v into 4 accumulators (paired-edge
// gathers: 2 groups of 16 lanes, group g takes edges e+2j+g, lane slot c owns
// 8B of the 128B row). Returns combined sums in lanes of group 0.
// ---------------------------------------------------------------------------
__device__ __forceinline__ void agg_node(const uint2* __restrict__ xw, int v,
                                         int g, int c,
                                         float& ax0, float& ay0,
                                         float& ax1, float& ay1) {
    ax0 = ay0 = ax1 = ay1 = 0.f;
    if (g == 0) {   // self-loop message
        uint2 m = __ldg(&xw[v * 16 + c]);
        float2 a = h2f2(m.x), b = h2f2(m.y);
        ax0 = a.x; ay0 = a.y; ax1 = b.x; ay1 = b.y;
    }
    int e = __ldg(&g_offs[v]);
    int end = __ldg(&g_offs[v + 1]);
    for (; e + 16 <= end; e += 16) {
        #pragma unroll
        for (int j = 0; j < 8; j++) {
            int idx = __ldg(&g_csr[e + 2 * j + g]);
            uint2 m = __ldg(&xw[idx * 16 + c]);
            float2 a = h2f2(m.x), b = h2f2(m.y);
            ax0 += a.x; ay0 += a.y; ax1 += b.x; ay1 += b.y;
        }
    }
    #pragma unroll
    for (int j = 0; j < 8; j++) {
        int ej = e + 2 * j + g;
        if (ej < end) {
            int idx = __ldg(&g_csr[ej]);
            uint2 m = __ldg(&xw[idx * 16 + c]);
            float2 a = h2f2(m.x), b = h2f2(m.y);
            ax0 += a.x; ay0 += a.y; ax1 += b.x; ay1 += b.y;
        }
    }
    ax0 += __shfl_down_sync(0xffffffffu, ax0, 16);
    ay0 += __shfl_down_sync(0xffffffffu, ay0, 16);
    ax1 += __shfl_down_sync(0xffffffffu, ax1, 16);
    ay1 += __shfl_down_sync(0xffffffffu, ay1, 16);
}

// ---------------------------------------------------------------------------
// FUSED agg1 + gemm2: block = 256 nodes, 256 threads (8 warps).
// Phase A: warp w aggregates nodes [w*32, w*32+32); h = relu(dv*acc + b1)
//          stored fp16 into the smem tile (never touches gmem).
// Phase B: wmma GEMM on the smem tile; m2 = fp16(dinv * (H @ W2)) -> Yh.
// ---------------------------------------------------------------------------
__global__ __launch_bounds__(256) void k_agg_gemm(const uint2* __restrict__ msg,
                                                  const float* __restrict__ bias,
                                                  const float* __restrict__ W,
                                                  __half* __restrict__ Yh, int n) {
    __shared__ __half Ws[64 * 64];          // W2 fp16, 8KB
    __shared__ __half Hs[256 * XLD];        // h tile fp16, 36KB
    __shared__ float  Sc[8][16 * SLD];      // per-warp epilogue scratch

    int t = threadIdx.x;
    int w = t >> 5, lane = t & 31;
    int g = lane >> 4, c = lane & 15;
    int row0 = blockIdx.x * 256;

    for (int i = t; i < 4096; i += 256) Ws[i] = __float2half(W[i]);

    // Phase A: aggregate 32 nodes per warp into Hs
    float4 bv;
    if (g == 0) bv = __ldg((const float4*)(bias + c * 4));
    for (int nl = 0; nl < 32; nl++) {
        int r = w * 32 + nl;
        int v = row0 + r;
        if (v < n) {
            float ax0, ay0, ax1, ay1;
            agg_node(msg, v, g, c, ax0, ay0, ax1, ay1);
            if (g == 0) {
                float dv = __ldg(&g_dinv[v]);
                float r0 = fmaxf(fmaf(ax0, dv, bv.x), 0.f);
                float r1 = fmaxf(fmaf(ay0, dv, bv.y), 0.f);
                float r2 = fmaxf(fmaf(ax1, dv, bv.z), 0.f);
                float r3 = fmaxf(fmaf(ay1, dv, bv.w), 0.f);
                uint2 o;
                o.x = h2_bits(__floats2half2_rn(r0, r1));
                o.y = h2_bits(__floats2half2_rn(r2, r3));
                *(uint2*)&Hs[r * XLD + c * 4] = o;
            }
        } else if (g == 0) {
            *(uint2*)&Hs[r * XLD + c * 4] = make_uint2(0u, 0u);
        }
    }
    __syncthreads();

    // Phase B: wmma GEMM from Hs
    wmma::fragment<wmma::accumulator, 16, 16, 16, float> acc[2][4];
    #pragma unroll
    for (int mt = 0; mt < 2; mt++)
        #pragma unroll
        for (int nt = 0; nt < 4; nt++)
            wmma::fill_fragment(acc[mt][nt], 0.f);

    int mrow = w * 32;
    #pragma unroll
    for (int kc = 0; kc < 4; kc++) {
        wmma::fragment<wmma::matrix_a, 16, 16, 16, __half, wmma::row_major> af[2];
        wmma::load_matrix_sync(af[0], &Hs[mrow * XLD + kc * 16], XLD);
        wmma::load_matrix_sync(af[1], &Hs[(mrow + 16) * XLD + kc * 16], XLD);
        #pragma unroll
        for (int nt = 0; nt < 4; nt++) {
            wmma::fragment<wmma::matrix_b, 16, 16, 16, __half, wmma::row_major> bf;
            wmma::load_matrix_sync(bf, &Ws[(kc * 16) * 64 + nt * 16], 64);
            wmma::mma_sync(acc[0][nt], af[0], bf, acc[0][nt]);
            wmma::mma_sync(acc[1][nt], af[1], bf, acc[1][nt]);
        }
    }

    #pragma unroll
    for (int mt = 0; mt < 2; mt++) {
        #pragma unroll
        for (int nt = 0; nt < 4; nt++) {
            wmma::store_matrix_sync(&Sc[w][0], acc[mt][nt], SLD, wmma::mem_row_major);
            __syncwarp();
            int r = lane >> 1;
            int cb = (lane & 1) * 8;
            int gr = row0 + mrow + mt * 16 + r;
            if (gr < n) {
                float dv = __ldg(&g_dinv[gr]);
                const float* s = &Sc[w][r * SLD + cb];
                uint4 pk;
                pk.x = h2_bits(__floats2half2_rn(s[0] * dv, s[1] * dv));
                pk.y = h2_bits(__floats2half2_rn(s[2] * dv, s[3] * dv));
                pk.z = h2_bits(__floats2half2_rn(s[4] * dv, s[5] * dv));
                pk.w = h2_bits(__floats2half2_rn(s[6] * dv, s[7] * dv));
                *(uint4*)&Yh[gr * 64 + nt * 16 + cb] = pk;
            }
            __syncwarp();
        }
    }
}

// ---------------------------------------------------------------------------
// Tensor-core GEMM (layer 1, fp32 input) + fused dinv-scale + fp16 store.
// ---------------------------------------------------------------------------
__global__ __launch_bounds__(256) void k_gemm64t(const float* __restrict__ X,
                                                 const float* __restrict__ W,
                                                 __half* __restrict__ Yh, int n) {
    __shared__ __half Ws[64 * 64];
    __shared__ __half Xs[256 * XLD];
    __shared__ float  Sc[8][16 * SLD];

    int t = threadIdx.x;
    int w = t >> 5, lane = t & 31;
    int row0 = blockIdx.x * 256;

    for (int i = t; i < 4096; i += 256) Ws[i] = __float2half(W[i]);
    for (int i = t; i < 16384; i += 256) {
        int r = i >> 6, c = i & 63;
        int gr = row0 + r;
        float xv = (gr < n) ? X[gr * 64 + c] : 0.f;
        Xs[r * XLD + c] = __float2half(xv);
    }
    __syncthreads();

    wmma::fragment<wmma::accumulator, 16, 16, 16, float> acc[2][4];
    #pragma unroll
    for (int mt = 0; mt < 2; mt++)
        #pragma unroll
        for (int nt = 0; nt < 4; nt++)
            wmma::fill_fragment(acc[mt][nt], 0.f);

    int mrow = w * 32;
    #pragma unroll
    for (int kc = 0; kc < 4; kc++) {
        wmma::fragment<wmma::matrix_a, 16, 16, 16, __half, wmma::row_major> af[2];
        wmma::load_matrix_sync(af[0], &Xs[mrow * XLD + kc * 16], XLD);
        wmma::load_matrix_sync(af[1], &Xs[(mrow + 16) * XLD + kc * 16], XLD);
        #pragma unroll
        for (int nt = 0; nt < 4; nt++) {
            wmma::fragment<wmma::matrix_b, 16, 16, 16, __half, wmma::row_major> bf;
            wmma::load_matrix_sync(bf, &Ws[(kc * 16) * 64 + nt * 16], 64);
            wmma::mma_sync(acc[0][nt], af[0], bf, acc[0][nt]);
            wmma::mma_sync(acc[1][nt], af[1], bf, acc[1][nt]);
        }
    }

    #pragma unroll
    for (int mt = 0; mt < 2; mt++) {
        #pragma unroll
        for (int nt = 0; nt < 4; nt++) {
            wmma::store_matrix_sync(&Sc[w][0], acc[mt][nt], SLD, wmma::mem_row_major);
            __syncwarp();
            int r = lane >> 1;
            int cb = (lane & 1) * 8;
            int gr = row0 + mrow + mt * 16 + r;
            if (gr < n) {
                float dv = __ldg(&g_dinv[gr]);
                const float* s = &Sc[w][r * SLD + cb];
                uint4 pk;
                pk.x = h2_bits(__floats2half2_rn(s[0] * dv, s[1] * dv));
                pk.y = h2_bits(__floats2half2_rn(s[2] * dv, s[3] * dv));
                pk.z = h2_bits(__floats2half2_rn(s[4] * dv, s[5] * dv));
                pk.w = h2_bits(__floats2half2_rn(s[6] * dv, s[7] * dv));
                *(uint4*)&Yh[gr * 64 + nt * 16 + cb] = pk;
            }
            __syncwarp();
        }
    }
}

// ---------------------------------------------------------------------------
// Final aggregation (layer 2): warp = node, fp32 output.
// ---------------------------------------------------------------------------
__global__ __launch_bounds__(256) void k_agg2(const uint2* __restrict__ xw,
                                              const float* __restrict__ bias,
                                              float* __restrict__ out, int n) {
    int v = (blockIdx.x * 256 + threadIdx.x) >> 5;
    int lane = threadIdx.x & 31;
    if (v >= n) return;
    int g = lane >> 4, c = lane & 15;

    float ax0, ay0, ax1, ay1;
    agg_node(xw, v, g, c, ax0, ay0, ax1, ay1);

    if (g == 0) {
        float dv = g_dinv[v];
        float4 bv = __ldg((const float4*)(bias + c * 4));
        float r0 = fmaxf(fmaf(ax0, dv, bv.x), 0.f);
        float r1 = fmaxf(fmaf(ay0, dv, bv.y), 0.f);
        float r2 = fmaxf(fmaf(ax1, dv, bv.z), 0.f);
        float r3 = fmaxf(fmaf(ay1, dv, bv.w), 0.f);
        ((float4*)out)[v * 16 + c] = make_float4(r0, r1, r2, r3);
    }
}

// ---------------------------------------------------------------------------
extern "C" void kernel_launch(void* const* d_in, const int* in_sizes, int n_in,
                              void* d_out, int out_size) {
    const float* x  = (const float*)d_in[0];
    const int*   ei = (const int*)d_in[1];
    const float* W1 = (const float*)d_in[2];
    const float* b1 = (const float*)d_in[3];
    const float* W2 = (const float*)d_in[4];
    const float* b2 = (const float*)d_in[5];
    float* out = (float*)d_out;

    int N = in_sizes[0] / 64;
    int E = in_sizes[1] / 2;
    const int* src = ei;
    const int* dst = ei + E;
    int E4 = E / 4;

    int nbN = (N + 255) / 256;
    int nbE4 = (E4 + 255) / 256;
    int nbScan = (N + 1023) / 1024;
    int nbAgg = (N + 7) / 8;        // 8 warps per 256-thread block
    int nbTile = (N + 255) / 256;   // 256 rows per tensor-core / fused block

    __half* hbuf;  cudaGetSymbolAddress((void**)&hbuf, g_hbuf);
    __half* hact;  cudaGetSymbolAddress((void**)&hact, g_hact);

    // One-time side stream + events (created on the pre-capture correctness
    // call; reused by every call -> identical, deterministic launch pattern).
    static cudaStream_t s1 = nullptr;
    static cudaEvent_t evFork = nullptr, evJoin = nullptr;
    static bool streamsOk = false;
    static bool tried = false;
    if (!tried) {
        tried = true;
        streamsOk = (cudaStreamCreateWithFlags(&s1, cudaStreamNonBlocking) == cudaSuccess) &&
                    (cudaEventCreateWithFlags(&evFork, cudaEventDisableTiming) == cudaSuccess) &&
                    (cudaEventCreateWithFlags(&evJoin, cudaEventDisableTiming) == cudaSuccess);
    }

    // CSR build prologue. indeg starts zero (globals on call 1, re-zeroed by
    // scan3 on every call).
    k_hist<<<nbE4, 256>>>(dst, E);
    k_scan1<<<nbScan, 1024>>>(N);   // also produces dinv

    if (streamsOk) {
        // Fork: GEMM1 (needs dinv only) overlaps scan3+fill on main stream.
        cudaEventRecord(evFork, 0);
        cudaStreamWaitEvent(s1, evFork, 0);
        k_gemm64t<<<nbTile, 256, 0, s1>>>(x, W1, hbuf, N);
        cudaEventRecord(evJoin, s1);

        k_scan3<<<nbN, 256>>>(N);
        k_fill<<<nbE4, 256>>>(src, dst, E);

        cudaStreamWaitEvent(0, evJoin, 0);
    } else {
        k_gemm64t<<<nbTile, 256>>>(x, W1, hbuf, N);
        k_scan3<<<nbN, 256>>>(N);
        k_fill<<<nbE4, 256>>>(src, dst, E);
    }

    // Fused layer-1 aggregate + layer-2 GEMM (h never touches gmem)
    k_agg_gemm<<<nbTile, 256>>>((const uint2*)hbuf, b1, W2, hact, N);

    // Final aggregation
    k_agg2<<<nbAgg, 256>>>((const uint2*)hact, b2, out, N);
}

// round 14
// speedup vs baseline: 1.2284x; 1.2284x over previous
#include <cuda_runtime.h>
#include <cuda_fp16.h>

// Fixed problem shape (SimpleGNN): N=100000 nodes, E=1600000 edges, dims 64->64->64
#define MAXN 100000
#define MAXE 1600000

// Scratch (device globals -- no runtime allocation allowed)
__device__ __half g_hbuf[MAXN * 64];   // fp16 m1 message table (gemm1 out, agg1 in)
__device__ __half g_hact[MAXN * 64];   // fp16 hidden activations h (agg1 out, gemm2 in)
__device__ __half g_hbuf2[MAXN * 64];  // fp16 m2 message table (gemm2 out, agg2 in)
__device__ int    g_indeg[MAXN];       // re-zeroed in k_scan3 (replay invariant)
__device__ int    g_incl[MAXN];
__device__ int    g_offs[MAXN + 1];    // exclusive offsets (immutable after scan3)
__device__ int    g_rank[MAXE];        // within-node rank of each edge (from hist)
__device__ int    g_csr[MAXE];         // src index only (weight folded into message)
__device__ float  g_dinv[MAXN];
__device__ int    g_bsums[128];        // per-1024-block totals from scan1

// ---------------------------------------------------------------------------
// f32x2 packed-FMA helpers (sm_10x FFMA2 -- only reachable via PTX)
// ---------------------------------------------------------------------------
__device__ __forceinline__ void ffma2(unsigned long long& acc,
                                      unsigned long long a, unsigned long long b) {
    asm("fma.rn.f32x2 %0, %1, %2, %0;" : "+l"(acc) : "l"(a), "l"(b));
}
__device__ __forceinline__ unsigned long long pack2(float v) {
    unsigned long long r;
    asm("mov.b64 %0, {%1, %1};" : "=l"(r) : "f"(v));
    return r;
}
__device__ __forceinline__ float2 unpack2(unsigned long long v) {
    float2 r;
    asm("mov.b64 {%0, %1}, %2;" : "=f"(r.x), "=f"(r.y) : "l"(v));
    return r;
}
__device__ __forceinline__ unsigned h2_bits(__half2 h) {
    return *reinterpret_cast<unsigned*>(&h);
}
__device__ __forceinline__ float2 h2f2(unsigned bits) {
    return __half22float2(*reinterpret_cast<__half2*>(&bits));
}

// ---------------------------------------------------------------------------
// Histogram of in-degrees + per-edge rank (position within its node's segment)
// ---------------------------------------------------------------------------
__global__ void k_hist(const int* __restrict__ dst, int E) {
    int i = (blockIdx.x * blockDim.x + threadIdx.x) * 4;
    if (i + 4 <= E) {
        int4 d = __ldg((const int4*)(dst + i));
        int4 r;
        r.x = atomicAdd(&g_indeg[d.x], 1);
        r.y = atomicAdd(&g_indeg[d.y], 1);
        r.z = atomicAdd(&g_indeg[d.z], 1);
        r.w = atomicAdd(&g_indeg[d.w], 1);
        *(int4*)(g_rank + i) = r;
    } else {
        for (; i < E; i++) g_rank[i] = atomicAdd(&g_indeg[dst[i]], 1);
    }
}

// Block-wise inclusive scan of indeg (shfl); block totals -> g_bsums.
// Also emits dinv = rsqrt(indeg+1) so GEMM1 can fork right after this kernel.
__global__ __launch_bounds__(1024) void k_scan1(int n) {
    __shared__ int wsum[32];
    int t = threadIdx.x, lane = t & 31, w = t >> 5;
    int i = blockIdx.x * 1024 + t;
    int v = (i < n) ? g_indeg[i] : 0;
    int x = v;
    #pragma unroll
    for (int d = 1; d < 32; d <<= 1) {
        int y = __shfl_up_sync(0xffffffffu, x, d);
        if (lane >= d) x += y;
    }
    if (lane == 31) wsum[w] = x;
    __syncthreads();
    if (w == 0) {
        int y = wsum[lane];
        int z = y;
        #pragma unroll
        for (int d = 1; d < 32; d <<= 1) {
            int u = __shfl_up_sync(0xffffffffu, z, d);
            if (lane >= d) z += u;
        }
        wsum[lane] = z - y;  // exclusive warp offsets
    }
    __syncthreads();
    x += wsum[w];
    if (i < n) {
        g_incl[i] = x;
        g_dinv[i] = rsqrtf((float)(v + 1));
    }
    if (t == 1023) g_bsums[blockIdx.x] = x;
}

// Offsets: each 256-block lies in one 1024-chunk; warp 0 reduces bsums[0..chunk)
// (<=98 ints). Re-zeroes indeg for the next replay.
__global__ void k_scan3(int n) {
    __shared__ int s_pre;
    int chunk = (blockIdx.x * 256) >> 10;
    if (threadIdx.x < 32) {
        int acc = 0;
        for (int k = threadIdx.x; k < chunk; k += 32) acc += g_bsums[k];
        #pragma unroll
        for (int d = 16; d >= 1; d >>= 1) acc += __shfl_down_sync(0xffffffffu, acc, d);
        if (threadIdx.x == 0) s_pre = acc;
    }
    __syncthreads();
    int i = blockIdx.x * 256 + threadIdx.x;
    if (i < n) {
        int ind = g_indeg[i];
        int base = s_pre + g_incl[i];
        g_offs[i] = base - ind;
        if (i == n - 1) g_offs[n] = base;
        g_indeg[i] = 0;                      // ready for next replay
    }
}

// Atomic-free scatter: pos = offs[dst] + rank (rank precomputed in hist).
__global__ void k_fill(const int* __restrict__ src, const int* __restrict__ dst, int E) {
    int i = (blockIdx.x * blockDim.x + threadIdx.x) * 4;
    if (i + 4 <= E) {
        int4 s = __ldg((const int4*)(src + i));
        int4 d = __ldg((const int4*)(dst + i));
        int4 r = *(const int4*)(g_rank + i);
        g_csr[__ldg(&g_offs[d.x]) + r.x] = s.x;
        g_csr[__ldg(&g_offs[d.y]) + r.y] = s.y;
        g_csr[__ldg(&g_offs[d.z]) + r.z] = s.z;
        g_csr[__ldg(&g_offs[d.w]) + r.w] = s.w;
    } else {
        for (; i < E; i++) {
            g_csr[__ldg(&g_offs[dst[i]]) + g_rank[i]] = src[i];
        }
    }
}

// ---------------------------------------------------------------------------
// GEMM + fused dinv-scale + fp16 store: m[r] = fp16(dinv[r] * (X@W)[r]).
// T = float (layer 1 input) or __half (layer 2 input).
// 128 threads/block, 128 rows/block; 8x8 tile/thread via packed f32x2 FMA.
// rbase: starting row (for row-range pipelining).
// ---------------------------------------------------------------------------
template <typename T>
__global__ __launch_bounds__(128) void k_gemm64h(const T* __restrict__ X,
                                                 const float* __restrict__ W,
                                                 __half* __restrict__ Yh,
                                                 int rbase, int n) {
    __shared__ float Ws[64 * 64];
    __shared__ float Xs[128 * 65];  // pad to 65 to avoid bank conflicts

    int t = threadIdx.x;
    #pragma unroll
    for (int i = t; i < 4096; i += 128) Ws[i] = W[i];

    int row0 = rbase + blockIdx.x * 128;
    for (int i = t; i < 8192; i += 128) {
        int r = i >> 6, c = i & 63;
        int gr = row0 + r;
        Xs[r * 65 + c] = (gr < n) ? (float)X[gr * 64 + c] : 0.f;
    }
    __syncthreads();

    int cg = t & 7;       // column group: cols [cg*8, cg*8+8)
    int rg = t >> 3;      // row group:    rows [rg*8, rg*8+8)

    unsigned long long acc[8][4];
    #pragma unroll
    for (int i = 0; i < 8; i++)
        #pragma unroll
        for (int j = 0; j < 4; j++) acc[i][j] = 0ull;

    #pragma unroll 4
    for (int k = 0; k < 64; k++) {
        ulonglong2 wA = *(const ulonglong2*)&Ws[k * 64 + cg * 8];
        ulonglong2 wB = *(const ulonglong2*)&Ws[k * 64 + cg * 8 + 4];
        #pragma unroll
        for (int i = 0; i < 8; i++) {
            unsigned long long xp = pack2(Xs[(rg * 8 + i) * 65 + k]);
            ffma2(acc[i][0], xp, wA.x);
            ffma2(acc[i][1], xp, wA.y);
            ffma2(acc[i][2], xp, wB.x);
            ffma2(acc[i][3], xp, wB.y);
        }
    }

    #pragma unroll
    for (int i = 0; i < 8; i++) {
        int gr = row0 + rg * 8 + i;
        if (gr < n) {
            float dv = __ldg(&g_dinv[gr]);
            float2 p0 = unpack2(acc[i][0]), p1 = unpack2(acc[i][1]);
            float2 p2 = unpack2(acc[i][2]), p3 = unpack2(acc[i][3]);
            uint4 pk;
            pk.x = h2_bits(__floats2half2_rn(p0.x * dv, p0.y * dv));
            pk.y = h2_bits(__floats2half2_rn(p1.x * dv, p1.y * dv));
            pk.z = h2_bits(__floats2half2_rn(p2.x * dv, p2.y * dv));
            pk.w = h2_bits(__floats2half2_rn(p3.x * dv, p3.y * dv));
            *(uint4*)&Yh[gr * 64 + cg * 8] = pk;
        }
    }
}

// ---------------------------------------------------------------------------
// Pull aggregation with paired-edge gathers (R9 champion configuration).
// Warp = 1 node; 2 groups of 16 lanes; group g handles edges (e+2j+g);
// each lane gathers 8B of the 128B row -> one LDG.64 covers TWO edges per j.
// Processes nodes [v0, vend) for pipelining.
// ---------------------------------------------------------------------------
template <bool HOUT>
__global__ __launch_bounds__(256) void k_agg(const uint2* __restrict__ xw,  // row = 16 uint2
                                             const float* __restrict__ bias,
                                             void* __restrict__ out,
                                             int v0, int vend) {
    int v = v0 + ((blockIdx.x * 256 + threadIdx.x) >> 5);
    int lane = threadIdx.x & 31;
    if (v >= vend) return;
    int g = lane >> 4;       // edge-parity group (0: even edges, 1: odd edges)
    int c = lane & 15;       // 8-byte column slot within the 128B row

    float dv = g_dinv[v];
    float ax0 = 0.f, ay0 = 0.f, ax1 = 0.f, ay1 = 0.f;

    // self-loop message: group 0 only
    if (g == 0) {
        uint2 m = __ldg(&xw[v * 16 + c]);
        float2 a = h2f2(m.x), b = h2f2(m.y);
        ax0 = a.x; ay0 = a.y; ax1 = b.x; ay1 = b.y;
    }

    int e = __ldg(&g_offs[v]);
    int end = __ldg(&g_offs[v + 1]);

    // full batches: 16 edges (8 pairs) per iteration, 8 independent LDG.64
    for (; e + 16 <= end; e += 16) {
        #pragma unroll
        for (int j = 0; j < 8; j++) {
            int idx = __ldg(&g_csr[e + 2 * j + g]);
            uint2 m = __ldg(&xw[idx * 16 + c]);
            float2 a = h2f2(m.x), b = h2f2(m.y);
            ax0 += a.x; ay0 += a.y; ax1 += b.x; ay1 += b.y;
        }
    }
    // predicated tail: remaining <16 edges, still 8-deep in flight
    #pragma unroll
    for (int j = 0; j < 8; j++) {
        int ej = e + 2 * j + g;
        if (ej < end) {
            int idx = __ldg(&g_csr[ej]);
            uint2 m = __ldg(&xw[idx * 16 + c]);
            float2 a = h2f2(m.x), b = h2f2(m.y);
            ax0 += a.x; ay0 += a.y; ax1 += b.x; ay1 += b.y;
        }
    }

    // combine the two edge groups
    ax0 += __shfl_down_sync(0xffffffffu, ax0, 16);
    ay0 += __shfl_down_sync(0xffffffffu, ay0, 16);
    ax1 += __shfl_down_sync(0xffffffffu, ax1, 16);
    ay1 += __shfl_down_sync(0xffffffffu, ay1, 16);

    if (g == 0) {
        float4 bv = __ldg((const float4*)(bias + c * 4));
        float r0 = fmaxf(fmaf(ax0, dv, bv.x), 0.f);
        float r1 = fmaxf(fmaf(ay0, dv, bv.y), 0.f);
        float r2 = fmaxf(fmaf(ax1, dv, bv.z), 0.f);
        float r3 = fmaxf(fmaf(ay1, dv, bv.w), 0.f);
        if (HOUT) {
            uint2 o;
            o.x = h2_bits(__floats2half2_rn(r0, r1));
            o.y = h2_bits(__floats2half2_rn(r2, r3));
            ((uint2*)out)[v * 16 + c] = o;
        } else {
            ((float4*)out)[v * 16 + c] = make_float4(r0, r1, r2, r3);
        }
    }
}

// ---------------------------------------------------------------------------
extern "C" void kernel_launch(void* const* d_in, const int* in_sizes, int n_in,
                              void* d_out, int out_size) {
    const float* x  = (const float*)d_in[0];
    const int*   ei = (const int*)d_in[1];
    const float* W1 = (const float*)d_in[2];
    const float* b1 = (const float*)d_in[3];
    const float* W2 = (const float*)d_in[4];
    const float* b2 = (const float*)d_in[5];
    float* out = (float*)d_out;

    int N = in_sizes[0] / 64;
    int E = in_sizes[1] / 2;
    const int* src = ei;
    const int* dst = ei + E;
    int E4 = E / 4;

    int nbN = (N + 255) / 256;
    int nbE4 = (E4 + 255) / 256;
    int nbScan = (N + 1023) / 1024;
    int nbGemm = (N + 127) / 128;

    // split point for agg1/gemm2 pipelining (multiple of 128 rows & 8 nodes)
    int Nh = ((N / 2 + 127) / 128) * 128;
    if (Nh > N) Nh = N;
    int nbAggA = (Nh + 7) / 8;
    int nbAggB = (N - Nh + 7) / 8;
    int nbGemmA = (Nh + 127) / 128;
    int nbGemmB = (N - Nh + 127) / 128;
    int nbAggAll = (N + 7) / 8;

    __half* hbuf;   cudaGetSymbolAddress((void**)&hbuf, g_hbuf);
    __half* hact;   cudaGetSymbolAddress((void**)&hact, g_hact);
    __half* hbuf2;  cudaGetSymbolAddress((void**)&hbuf2, g_hbuf2);

    // One-time side stream + events (created on the pre-capture correctness
    // call; reused by every call -> identical, deterministic launch pattern).
    static cudaStream_t s1 = nullptr;
    static cudaEvent_t evFork = nullptr, evJoin = nullptr, evA = nullptr, evG = nullptr;
    static bool streamsOk = false;
    static bool tried = false;
    if (!tried) {
        tried = true;
        streamsOk = (cudaStreamCreateWithFlags(&s1, cudaStreamNonBlocking) == cudaSuccess) &&
                    (cudaEventCreateWithFlags(&evFork, cudaEventDisableTiming) == cudaSuccess) &&
                    (cudaEventCreateWithFlags(&evJoin, cudaEventDisableTiming) == cudaSuccess) &&
                    (cudaEventCreateWithFlags(&evA, cudaEventDisableTiming) == cudaSuccess) &&
                    (cudaEventCreateWithFlags(&evG, cudaEventDisableTiming) == cudaSuccess);
    }

    // CSR build prologue. indeg starts zero (globals on call 1, re-zeroed by
    // scan3 on every call).
    k_hist<<<nbE4, 256>>>(dst, E);
    k_scan1<<<nbScan, 1024>>>(N);   // also produces dinv

    if (streamsOk) {
        // Fork: GEMM1 (needs dinv only) overlaps scan3+fill on main stream.
        cudaEventRecord(evFork, 0);
        cudaStreamWaitEvent(s1, evFork, 0);
        k_gemm64h<float><<<nbGemm, 128, 0, s1>>>(x, W1, hbuf, 0, N);
        cudaEventRecord(evJoin, s1);

        k_scan3<<<nbN, 256>>>(N);
        k_fill<<<nbE4, 256>>>(src, dst, E);

        cudaStreamWaitEvent(0, evJoin, 0);

        // Pipelined agg1 / gemm2 across node halves. Buffers are disjoint:
        //   hbuf  = m1 (read-only here), hact = h (by row range), hbuf2 = m2.
        //   main: agg1_A -> agg1_B -> gemm2_B -> (wait gemm2_A) -> agg2
        //   side: (wait agg1_A) gemm2_A
        k_agg<true><<<nbAggA, 256>>>((const uint2*)hbuf, b1, hact, 0, Nh);
        cudaEventRecord(evA, 0);
        cudaStreamWaitEvent(s1, evA, 0);
        k_gemm64h<__half><<<nbGemmA, 128, 0, s1>>>(hact, W2, hbuf2, 0, Nh);
        cudaEventRecord(evG, s1);

        k_agg<true><<<nbAggB, 256>>>((const uint2*)hbuf, b1, hact, Nh, N);
        k_gemm64h<__half><<<nbGemmB, 128>>>(hact, W2, hbuf2, Nh, N);
        cudaStreamWaitEvent(0, evG, 0);

        k_agg<false><<<nbAggAll, 256>>>((const uint2*)hbuf2, b2, out, 0, N);
    } else {
        k_gemm64h<float><<<nbGemm, 128>>>(x, W1, hbuf, 0, N);
        k_scan3<<<nbN, 256>>>(N);
        k_fill<<<nbE4, 256>>>(src, dst, E);
        k_agg<true><<<nbAggAll, 256>>>((const uint2*)hbuf, b1, hact, 0, N);
        k_gemm64h<__half><<<nbGemm, 128>>>(hact, W2, hbuf2, 0, N);
        k_agg<false><<<nbAggAll, 256>>>((const uint2*)hbuf2, b2, out, 0, N);
    }
}

// round 15
// speedup vs baseline: 1.2608x; 1.0263x over previous
#include <cuda_runtime.h>
#include <cuda_fp16.h>

// Fixed problem shape (SimpleGNN): N=100000 nodes, E=1600000 edges, dims 64->64->64
#define MAXN 100000
#define MAXE 1600000

// Scratch (device globals -- no runtime allocation allowed)
__device__ __half g_hbuf[MAXN * 64];   // fp16 pre-scaled message table
__device__ __half g_hact[MAXN * 64];   // fp16 hidden activations (layer-1 output)
__device__ int    g_indeg[MAXN];       // re-zeroed in k_scan3 (replay invariant)
__device__ int    g_incl[MAXN];
__device__ int    g_offs[MAXN + 1];    // exclusive offsets (immutable after scan3)
__device__ unsigned short g_rank[MAXE];// within-node rank of each edge (from hist)
__device__ int    g_csr[MAXE];         // src index only (weight folded into message)
__device__ float  g_dinv[MAXN];
__device__ int    g_bsums[128];        // per-1024-block totals from scan1

// ---------------------------------------------------------------------------
// f32x2 packed-FMA helpers (sm_10x FFMA2 -- only reachable via PTX)
// ---------------------------------------------------------------------------
__device__ __forceinline__ void ffma2(unsigned long long& acc,
                                      unsigned long long a, unsigned long long b) {
    asm("fma.rn.f32x2 %0, %1, %2, %0;" : "+l"(acc) : "l"(a), "l"(b));
}
__device__ __forceinline__ unsigned long long pack2(float v) {
    unsigned long long r;
    asm("mov.b64 %0, {%1, %1};" : "=l"(r) : "f"(v));
    return r;
}
__device__ __forceinline__ float2 unpack2(unsigned long long v) {
    float2 r;
    asm("mov.b64 {%0, %1}, %2;" : "=f"(r.x), "=f"(r.y) : "l"(v));
    return r;
}
__device__ __forceinline__ unsigned h2_bits(__half2 h) {
    return *reinterpret_cast<unsigned*>(&h);
}
__device__ __forceinline__ float2 h2f2(unsigned bits) {
    return __half22float2(*reinterpret_cast<__half2*>(&bits));
}

// ---------------------------------------------------------------------------
// Histogram of in-degrees + per-edge rank (ushort: max degree << 65536)
// ---------------------------------------------------------------------------
__global__ void k_hist(const int* __restrict__ dst, int E) {
    int i = (blockIdx.x * blockDim.x + threadIdx.x) * 4;
    if (i + 4 <= E) {
        int4 d = __ldg((const int4*)(dst + i));
        ushort4 r;
        r.x = (unsigned short)atomicAdd(&g_indeg[d.x], 1);
        r.y = (unsigned short)atomicAdd(&g_indeg[d.y], 1);
        r.z = (unsigned short)atomicAdd(&g_indeg[d.z], 1);
        r.w = (unsigned short)atomicAdd(&g_indeg[d.w], 1);
        *(ushort4*)(g_rank + i) = r;
    } else {
        for (; i < E; i++)
            g_rank[i] = (unsigned short)atomicAdd(&g_indeg[dst[i]], 1);
    }
}

// Block-wise inclusive scan of indeg (shfl); block totals -> g_bsums.
// Also emits dinv = rsqrt(indeg+1) so GEMM1 can fork right after this kernel.
__global__ __launch_bounds__(1024) void k_scan1(int n) {
    __shared__ int wsum[32];
    int t = threadIdx.x, lane = t & 31, w = t >> 5;
    int i = blockIdx.x * 1024 + t;
    int v = (i < n) ? g_indeg[i] : 0;
    int x = v;
    #pragma unroll
    for (int d = 1; d < 32; d <<= 1) {
        int y = __shfl_up_sync(0xffffffffu, x, d);
        if (lane >= d) x += y;
    }
    if (lane == 31) wsum[w] = x;
    __syncthreads();
    if (w == 0) {
        int y = wsum[lane];
        int z = y;
        #pragma unroll
        for (int d = 1; d < 32; d <<= 1) {
            int u = __shfl_up_sync(0xffffffffu, z, d);
            if (lane >= d) z += u;
        }
        wsum[lane] = z - y;  // exclusive warp offsets
    }
    __syncthreads();
    x += wsum[w];
    if (i < n) {
        g_incl[i] = x;
        g_dinv[i] = rsqrtf((float)(v + 1));
    }
    if (t == 1023) g_bsums[blockIdx.x] = x;
}

// Offsets: each 256-block lies in one 1024-chunk; warp 0 reduces bsums[0..chunk)
// (<=98 ints). Re-zeroes indeg for the next replay.
__global__ void k_scan3(int n) {
    __shared__ int s_pre;
    int chunk = (blockIdx.x * 256) >> 10;
    if (threadIdx.x < 32) {
        int acc = 0;
        for (int k = threadIdx.x; k < chunk; k += 32) acc += g_bsums[k];
        #pragma unroll
        for (int d = 16; d >= 1; d >>= 1) acc += __shfl_down_sync(0xffffffffu, acc, d);
        if (threadIdx.x == 0) s_pre = acc;
    }
    __syncthreads();
    int i = blockIdx.x * 256 + threadIdx.x;
    if (i < n) {
        int ind = g_indeg[i];
        int base = s_pre + g_incl[i];
        g_offs[i] = base - ind;
        if (i == n - 1) g_offs[n] = base;
        g_indeg[i] = 0;                      // ready for next replay
    }
}

// Atomic-free scatter: pos = offs[dst] + rank (rank precomputed in hist).
__global__ void k_fill(const int* __restrict__ src, const int* __restrict__ dst, int E) {
    int i = (blockIdx.x * blockDim.x + threadIdx.x) * 4;
    if (i + 4 <= E) {
        int4 s = __ldg((const int4*)(src + i));
        int4 d = __ldg((const int4*)(dst + i));
        ushort4 r = *(const ushort4*)(g_rank + i);
        g_csr[__ldg(&g_offs[d.x]) + r.x] = s.x;
        g_csr[__ldg(&g_offs[d.y]) + r.y] = s.y;
        g_csr[__ldg(&g_offs[d.z]) + r.z] = s.z;
        g_csr[__ldg(&g_offs[d.w]) + r.w] = s.w;
    } else {
        for (; i < E; i++) {
            g_csr[__ldg(&g_offs[dst[i]]) + g_rank[i]] = src[i];
        }
    }
}

// ---------------------------------------------------------------------------
// GEMM + fused dinv-scale + fp16 store: m[r] = fp16(dinv[r] * (X@W)[r]).
// T = float (layer 1 input) or __half (layer 2 input).
// 128 threads/block, 128 rows/block; 8x8 tile/thread via packed f32x2 FMA.
// ---------------------------------------------------------------------------
template <typename T>
__global__ __launch_bounds__(128) void k_gemm64h(const T* __restrict__ X,
                                                 const float* __restrict__ W,
                                                 __half* __restrict__ Yh, int n) {
    __shared__ float Ws[64 * 64];
    __shared__ float Xs[128 * 65];  // pad to 65 to avoid bank conflicts

    int t = threadIdx.x;
    #pragma unroll
    for (int i = t; i < 4096; i += 128) Ws[i] = W[i];

    int row0 = blockIdx.x * 128;
    for (int i = t; i < 8192; i += 128) {
        int r = i >> 6, c = i & 63;
        int gr = row0 + r;
        Xs[r * 65 + c] = (gr < n) ? (float)X[gr * 64 + c] : 0.f;
    }
    __syncthreads();

    int cg = t & 7;       // column group: cols [cg*8, cg*8+8)
    int rg = t >> 3;      // row group:    rows [rg*8, rg*8+8)

    unsigned long long acc[8][4];
    #pragma unroll
    for (int i = 0; i < 8; i++)
        #pragma unroll
        for (int j = 0; j < 4; j++) acc[i][j] = 0ull;

    #pragma unroll 4
    for (int k = 0; k < 64; k++) {
        ulonglong2 wA = *(const ulonglong2*)&Ws[k * 64 + cg * 8];
        ulonglong2 wB = *(const ulonglong2*)&Ws[k * 64 + cg * 8 + 4];
        #pragma unroll
        for (int i = 0; i < 8; i++) {
            unsigned long long xp = pack2(Xs[(rg * 8 + i) * 65 + k]);
            ffma2(acc[i][0], xp, wA.x);
            ffma2(acc[i][1], xp, wA.y);
            ffma2(acc[i][2], xp, wB.x);
            ffma2(acc[i][3], xp, wB.y);
        }
    }

    #pragma unroll
    for (int i = 0; i < 8; i++) {
        int gr = row0 + rg * 8 + i;
        if (gr < n) {
            float dv = __ldg(&g_dinv[gr]);
            float2 p0 = unpack2(acc[i][0]), p1 = unpack2(acc[i][1]);
            float2 p2 = unpack2(acc[i][2]), p3 = unpack2(acc[i][3]);
            uint4 pk;
            pk.x = h2_bits(__floats2half2_rn(p0.x * dv, p0.y * dv));
            pk.y = h2_bits(__floats2half2_rn(p1.x * dv, p1.y * dv));
            pk.z = h2_bits(__floats2half2_rn(p2.x * dv, p2.y * dv));
            pk.w = h2_bits(__floats2half2_rn(p3.x * dv, p3.y * dv));
            *(uint4*)&Yh[gr * 64 + cg * 8] = pk;
        }
    }
}

// ---------------------------------------------------------------------------
// Pull aggregation with QUAD-edge gathers.
// Warp = 1 node. Lanes split into 4 groups of 8: group q handles edges
// (e + 4j + q); each lane gathers 16B (uint4 = 8 halves) of the 128B source
// row -> one LDG.128 covers FOUR edges per j. A 32-edge batch = 8 LDGs in
// flight; nodes with deg <= 31 finish in ONE predicated batch.
// Combine groups via shfl_xor(8) + shfl_xor(16); group 0 writes out.
// ---------------------------------------------------------------------------
template <bool HOUT>
__global__ __launch_bounds__(256) void k_agg(const uint4* __restrict__ xw,  // row = 8 uint4
                                             const float* __restrict__ bias,
                                             void* __restrict__ out, int n) {
    int v = (blockIdx.x * 256 + threadIdx.x) >> 5;
    int lane = threadIdx.x & 31;
    if (v >= n) return;
    int q = lane >> 3;       // edge slot within a 4-edge pack
    int c = lane & 7;        // 16-byte column slot within the 128B row

    float dv = g_dinv[v];
    float a0 = 0.f, a1 = 0.f, a2 = 0.f, a3 = 0.f;
    float a4 = 0.f, a5 = 0.f, a6 = 0.f, a7 = 0.f;

    // self-loop message: group 0 only (8 lanes x 16B = one 128B row)
    if (q == 0) {
        uint4 m = __ldg(&xw[v * 8 + c]);
        float2 p0 = h2f2(m.x), p1 = h2f2(m.y), p2 = h2f2(m.z), p3 = h2f2(m.w);
        a0 = p0.x; a1 = p0.y; a2 = p1.x; a3 = p1.y;
        a4 = p2.x; a5 = p2.y; a6 = p3.x; a7 = p3.y;
    }

    int e = __ldg(&g_offs[v]);
    int end = __ldg(&g_offs[v + 1]);

    // full batches: 32 edges (8 quads) per iteration, 8 independent LDG.128
    for (; e + 32 <= end; e += 32) {
        #pragma unroll
        for (int j = 0; j < 8; j++) {
            int idx = __ldg(&g_csr[e + 4 * j + q]);
            uint4 m = __ldg(&xw[idx * 8 + c]);
            float2 p0 = h2f2(m.x), p1 = h2f2(m.y), p2 = h2f2(m.z), p3 = h2f2(m.w);
            a0 += p0.x; a1 += p0.y; a2 += p1.x; a3 += p1.y;
            a4 += p2.x; a5 += p2.y; a6 += p3.x; a7 += p3.y;
        }
    }
    // predicated tail: remaining <32 edges in one batch, still 8-deep in flight
    #pragma unroll
    for (int j = 0; j < 8; j++) {
        int ej = e + 4 * j + q;
        if (ej < end) {
            int idx = __ldg(&g_csr[ej]);
            uint4 m = __ldg(&xw[idx * 8 + c]);
            float2 p0 = h2f2(m.x), p1 = h2f2(m.y), p2 = h2f2(m.z), p3 = h2f2(m.w);
            a0 += p0.x; a1 += p0.y; a2 += p1.x; a3 += p1.y;
            a4 += p2.x; a5 += p2.y; a6 += p3.x; a7 += p3.y;
        }
    }

    // combine the four edge groups (lanes with same c, different q)
    a0 += __shfl_xor_sync(0xffffffffu, a0, 8);
    a1 += __shfl_xor_sync(0xffffffffu, a1, 8);
    a2 += __shfl_xor_sync(0xffffffffu, a2, 8);
    a3 += __shfl_xor_sync(0xffffffffu, a3, 8);
    a4 += __shfl_xor_sync(0xffffffffu, a4, 8);
    a5 += __shfl_xor_sync(0xffffffffu, a5, 8);
    a6 += __shfl_xor_sync(0xffffffffu, a6, 8);
    a7 += __shfl_xor_sync(0xffffffffu, a7, 8);
    a0 += __shfl_xor_sync(0xffffffffu, a0, 16);
    a1 += __shfl_xor_sync(0xffffffffu, a1, 16);
    a2 += __shfl_xor_sync(0xffffffffu, a2, 16);
    a3 += __shfl_xor_sync(0xffffffffu, a3, 16);
    a4 += __shfl_xor_sync(0xffffffffu, a4, 16);
    a5 += __shfl_xor_sync(0xffffffffu, a5, 16);
    a6 += __shfl_xor_sync(0xffffffffu, a6, 16);
    a7 += __shfl_xor_sync(0xffffffffu, a7, 16);

    if (q == 0) {
        float4 b0 = __ldg((const float4*)(bias + c * 8));
        float4 b1 = __ldg((const float4*)(bias + c * 8 + 4));
        float r0 = fmaxf(fmaf(a0, dv, b0.x), 0.f);
        float r1 = fmaxf(fmaf(a1, dv, b0.y), 0.f);
        float r2 = fmaxf(fmaf(a2, dv, b0.z), 0.f);
        float r3 = fmaxf(fmaf(a3, dv, b0.w), 0.f);
        float r4 = fmaxf(fmaf(a4, dv, b1.x), 0.f);
        float r5 = fmaxf(fmaf(a5, dv, b1.y), 0.f);
        float r6 = fmaxf(fmaf(a6, dv, b1.z), 0.f);
        float r7 = fmaxf(fmaf(a7, dv, b1.w), 0.f);
        if (HOUT) {
            uint4 o;
            o.x = h2_bits(__floats2half2_rn(r0, r1));
            o.y = h2_bits(__floats2half2_rn(r2, r3));
            o.z = h2_bits(__floats2half2_rn(r4, r5));
            o.w = h2_bits(__floats2half2_rn(r6, r7));
            ((uint4*)out)[v * 8 + c] = o;
        } else {
            float* op = (float*)out + v * 64 + c * 8;
            *(float4*)op = make_float4(r0, r1, r2, r3);
            *(float4*)(op + 4) = make_float4(r4, r5, r6, r7);
        }
    }
}

// ---------------------------------------------------------------------------
extern "C" void kernel_launch(void* const* d_in, const int* in_sizes, int n_in,
                              void* d_out, int out_size) {
    const float* x  = (const float*)d_in[0];
    const int*   ei = (const int*)d_in[1];
    const float* W1 = (const float*)d_in[2];
    const float* b1 = (const float*)d_in[3];
    const float* W2 = (const float*)d_in[4];
    const float* b2 = (const float*)d_in[5];
    float* out = (float*)d_out;

    int N = in_sizes[0] / 64;
    int E = in_sizes[1] / 2;
    const int* src = ei;
    const int* dst = ei + E;
    int E4 = E / 4;

    int nbN = (N + 255) / 256;
    int nbE4 = (E4 + 255) / 256;
    int nbScan = (N + 1023) / 1024;
    int nbAgg = (N + 7) / 8;       // 8 warps per 256-thread block
    int nbGemm = (N + 127) / 128;

    __half* hbuf;  cudaGetSymbolAddress((void**)&hbuf, g_hbuf);
    __half* hact;  cudaGetSymbolAddress((void**)&hact, g_hact);

    // One-time side stream + events (created on the pre-capture correctness
    // call; reused by every call -> identical, deterministic launch pattern).
    static cudaStream_t s1 = nullptr;
    static cudaEvent_t evFork = nullptr, evJoin = nullptr;
    static bool streamsOk = false;
    static bool tried = false;
    if (!tried) {
        tried = true;
        streamsOk = (cudaStreamCreateWithFlags(&s1, cudaStreamNonBlocking) == cudaSuccess) &&
                    (cudaEventCreateWithFlags(&evFork, cudaEventDisableTiming) == cudaSuccess) &&
                    (cudaEventCreateWithFlags(&evJoin, cudaEventDisableTiming) == cudaSuccess);
    }

    // CSR build prologue. indeg starts zero (globals on call 1, re-zeroed by
    // scan3 on every call).
    k_hist<<<nbE4, 256>>>(dst, E);
    k_scan1<<<nbScan, 1024>>>(N);   // also produces dinv

    if (streamsOk) {
        // Fork: GEMM1 (needs dinv only) overlaps scan3+fill on main stream.
        cudaEventRecord(evFork, 0);
        cudaStreamWaitEvent(s1, evFork, 0);
        k_gemm64h<float><<<nbGemm, 128, 0, s1>>>(x, W1, hbuf, N);
        cudaEventRecord(evJoin, s1);

        k_scan3<<<nbN, 256>>>(N);
        k_fill<<<nbE4, 256>>>(src, dst, E);

        cudaStreamWaitEvent(0, evJoin, 0);
    } else {
        k_gemm64h<float><<<nbGemm, 128>>>(x, W1, hbuf, N);
        k_scan3<<<nbN, 256>>>(N);
        k_fill<<<nbE4, 256>>>(src, dst, E);
    }

    // Layer 1 aggregate (fp16 h), then layer 2 (hbuf reused for m2 -- strictly
    // sequential on the main stream, so no overlap with agg1's reads)
    k_agg<true><<<nbAgg, 256>>>((const uint4*)hbuf, b1, hact, N);
    k_gemm64h<__half><<<nbGemm, 128>>>(hact, W2, hbuf, N);
    k_agg<false><<<nbAgg, 256>>>((const uint4*)hbuf, b2, out, N);
}